// round 7
// baseline (speedup 1.0000x reference)
#include <cuda_runtime.h>

// Problem constants
#define BB     16
#define NCTX   1024
#define NG     64          // grid points per axis (NX == NY == 64)
#define MROWS  192         // 64 i-rows * 3 channels
#define KSPL   8           // split-K factor
#define KCH    (NCTX/KSPL) // 128 n per CTA
#define KPAD   (KCH + 1)   // +1 row so prefetch of k+1 is always in-bounds

typedef unsigned long long u64;

// split-K partial results: [b][ks][m=192][j=64]
__device__ float    g_partial[BB * KSPL * MROWS * NG];
__device__ unsigned g_counter[BB];   // zero-initialized; reset in-kernel each launch

__device__ __forceinline__ void unpack2(u64 v, float& lo, float& hi) {
    unsigned a, b;
    asm("mov.b64 {%0, %1}, %2;" : "=r"(a), "=r"(b) : "l"(v));
    lo = __uint_as_float(a);
    hi = __uint_as_float(b);
}
__device__ __forceinline__ u64 mul2(u64 a, u64 b) {
    u64 d;
    asm("mul.rn.f32x2 %0, %1, %2;" : "=l"(d) : "l"(a), "l"(b));
    return d;
}
__device__ __forceinline__ u64 fma2(u64 a, u64 b, u64 c) {
    u64 d;
    asm("fma.rn.f32x2 %0, %1, %2, %3;" : "=l"(d) : "l"(a), "l"(b), "l"(c));
    return d;
}

// ---------------------------------------------------------------------------
// Fused kernel: exp + per-batch split-K GEMM (f32x2 FMA) + in-kernel split-K
// reduction by the last-arriving CTA of each batch.
//   Pd[n, 2j],Pd[n,2j+1] = exp(-0.5*(xs[j]-Xx)^2/l^2)   (pre-duplicated pairs)
//   Q [n, i]             = exp(-0.5*(ys[i]-Xy)^2/l^2)
//   eyd[n] = {y0,y0,y1,y1}
//   C[i*3+c, j] += sum_n Q[n,i]*ey_c[n]*P[n,j]
// Thread tile: 6 m-rows (i pair 2r,2r+1 x 3 ch) x 8 j-cols; acc paired along M.
// ---------------------------------------------------------------------------
__global__ void __launch_bounds__(256, 1)
equiv_fused_kernel(const float* __restrict__ X,
                   const float* __restrict__ Y,
                   const float* __restrict__ lls,
                   float* __restrict__ out)
{
    extern __shared__ float sm[];
    float* Pd_sm = sm;                              // [KPAD][128] dup pairs
    float* Q_sm  = sm + KPAD * 128;                 // [KPAD][64]
    float* eyd   = sm + KPAD * 128 + KPAD * 64;     // [KPAD][4]  {y0,y0,y1,y1}
    __shared__ int s_last;

    const int ks  = blockIdx.x;
    const int b   = blockIdx.y;
    const int tid = threadIdx.x;
    const int n0  = ks * KCH;

    const float invl2 = __expf(-2.0f * lls[0]);   // 1 / l^2
    const float step  = 20.0f / 63.0f;

    // ---- Phase A: P (duplicated), Q, eyd. Two threads per n-row. ----
    {
        const int nl = tid >> 1;
        const int wh = tid & 1;
        const int j0 = wh * 32;
        const int n  = b * NCTX + n0 + nl;
        const float xx = X[2 * n];
        const float xy = X[2 * n + 1];
        float* pr = Pd_sm + nl * 128;
        float* qr = Q_sm + nl * 64;
        #pragma unroll 8
        for (int j = j0; j < j0 + 32; ++j) {
            const float gx = -10.0f + (float)j * step;   // xs[j]
            const float gy =  10.0f - (float)j * step;   // ys[i]
            const float dx = gx - xx;
            const float dy = gy - xy;
            const float p  = __expf(-0.5f * dx * dx * invl2);
            pr[2 * j]     = p;
            pr[2 * j + 1] = p;
            qr[j] = __expf(-0.5f * dy * dy * invl2);
        }
        const float yv = Y[2 * n + wh];
        eyd[nl * 4 + 2 * wh]     = yv;
        eyd[nl * 4 + 2 * wh + 1] = yv;
    }
    __syncthreads();

    // ---- Phase B: GEMM with f32x2 packed FMA ----
    const int r  = tid & 31;    // m-tile: rows 6r..6r+5 (i = 2r, 2r+1)
    const int jb = (tid >> 5) * 8;

    u64 acc[3][8];
    #pragma unroll
    for (int c = 0; c < 3; ++c)
        #pragma unroll
        for (int v = 0; v < 8; ++v)
            acc[c][v] = 0ULL;

    // prefetch k=0 (all broadcast or coalesced LDS)
    u64        qq = *(const u64*)&Q_sm[2 * r];
    ulonglong2 ey = *(const ulonglong2*)&eyd[0];
    ulonglong2 p0 = *(const ulonglong2*)&Pd_sm[2 * jb];
    ulonglong2 p1 = *(const ulonglong2*)&Pd_sm[2 * jb + 4];
    ulonglong2 p2 = *(const ulonglong2*)&Pd_sm[2 * jb + 8];
    ulonglong2 p3 = *(const ulonglong2*)&Pd_sm[2 * jb + 12];

    #pragma unroll 2
    for (int k = 0; k < KCH; ++k) {
        const u64 qq_c = qq;
        const ulonglong2 ey_c = ey;
        const u64 pd[8] = {p0.x, p0.y, p1.x, p1.y, p2.x, p2.y, p3.x, p3.y};

        // prefetch k+1 (padded row makes this always in-bounds)
        qq = *(const u64*)&Q_sm[(k + 1) * 64 + 2 * r];
        ey = *(const ulonglong2*)&eyd[(k + 1) * 4];
        p0 = *(const ulonglong2*)&Pd_sm[(k + 1) * 128 + 2 * jb];
        p1 = *(const ulonglong2*)&Pd_sm[(k + 1) * 128 + 2 * jb + 4];
        p2 = *(const ulonglong2*)&Pd_sm[(k + 1) * 128 + 2 * jb + 8];
        p3 = *(const ulonglong2*)&Pd_sm[(k + 1) * 128 + 2 * jb + 12];

        const u64 m1 = mul2(qq_c, ey_c.x);   // {q0*y0, q1*y0}
        const u64 m2 = mul2(qq_c, ey_c.y);   // {q0*y1, q1*y1}

        #pragma unroll
        for (int v = 0; v < 8; ++v) {
            acc[0][v] = fma2(qq_c, pd[v], acc[0][v]);
            acc[1][v] = fma2(m1,   pd[v], acc[1][v]);
            acc[2][v] = fma2(m2,   pd[v], acc[2][v]);
        }
    }
    __syncthreads();

    // ---- Epilogue: stage C in smem, coalesced store of this split-K partial
    float* C_sm = sm;   // 12288 floats, reuses Pd region
    #pragma unroll
    for (int c = 0; c < 3; ++c)
        #pragma unroll
        for (int v = 0; v < 8; ++v) {
            float lo, hi;
            unpack2(acc[c][v], lo, hi);
            C_sm[(6 * r + c)     * 64 + jb + v] = lo;   // i = 2r
            C_sm[(6 * r + 3 + c) * 64 + jb + v] = hi;   // i = 2r+1
        }
    __syncthreads();

    {
        float4* dst = (float4*)(g_partial + (size_t)(b * KSPL + ks) * (MROWS * NG));
        const float4* src = (const float4*)C_sm;
        #pragma unroll
        for (int idx = tid; idx < MROWS * NG / 4; idx += 256)
            dst[idx] = src[idx];
    }

    // ---- Split-K tail: last CTA of this batch reduces + normalizes ----
    __threadfence();
    __syncthreads();
    if (tid == 0) {
        const unsigned v = atomicAdd(&g_counter[b], 1u);
        s_last = (v == KSPL - 1);
        if (s_last) g_counter[b] = 0;   // reset for next graph replay
    }
    __syncthreads();
    if (!s_last) return;

    __threadfence();   // acquire: partials of peer CTAs are visible
    for (int pos = tid; pos < NG * NG / 4; pos += 256) {
        const int i  = pos >> 4;
        const int j4 = (pos & 15) * 4;

        float4 s0 = make_float4(0.f, 0.f, 0.f, 0.f);
        float4 s1 = s0, s2 = s0;
        #pragma unroll
        for (int s = 0; s < KSPL; ++s) {
            const float* p = g_partial +
                ((size_t)(b * KSPL + s) * MROWS + i * 3) * NG + j4;
            const float4 v0 = __ldcv((const float4*)(p));
            const float4 v1 = __ldcv((const float4*)(p + NG));
            const float4 v2 = __ldcv((const float4*)(p + 2 * NG));
            s0.x += v0.x; s0.y += v0.y; s0.z += v0.z; s0.w += v0.w;
            s1.x += v1.x; s1.y += v1.y; s1.z += v1.z; s1.w += v1.w;
            s2.x += v2.x; s2.y += v2.y; s2.z += v2.z; s2.w += v2.w;
        }

        const int base = i * 64 + j4;
        float4 o1 = make_float4(s1.x / s0.x, s1.y / s0.y, s1.z / s0.z, s1.w / s0.w);
        float4 o2 = make_float4(s2.x / s0.x, s2.y / s0.y, s2.z / s0.z, s2.w / s0.w);
        *(float4*)&out[(b * 3 + 0) * 4096 + base] = s0;
        *(float4*)&out[(b * 3 + 1) * 4096 + base] = o1;
        *(float4*)&out[(b * 3 + 2) * 4096 + base] = o2;
    }
}

// ---------------------------------------------------------------------------
extern "C" void kernel_launch(void* const* d_in, const int* in_sizes, int n_in,
                              void* d_out, int out_size)
{
    const float* X   = (const float*)d_in[0];
    const float* Y   = (const float*)d_in[1];
    const float* lls = (const float*)d_in[2];
    float* out = (float*)d_out;

    const size_t smem_bytes = (size_t)(KPAD * 128 + KPAD * 64 + KPAD * 4) * sizeof(float);
    cudaFuncSetAttribute(equiv_fused_kernel,
                         cudaFuncAttributeMaxDynamicSharedMemorySize,
                         (int)smem_bytes);

    equiv_fused_kernel<<<dim3(KSPL, BB), 256, smem_bytes>>>(X, Y, lls, out);
}

// round 8
// speedup vs baseline: 1.1491x; 1.1491x over previous
#include <cuda_runtime.h>

// Problem constants
#define BB     16
#define NCTX   1024
#define NG     64          // grid points per axis (NX == NY == 64)
#define MROWS  192         // 64 i-rows * 3 channels
#define KSPL   8           // split-K factor
#define KCH    (NCTX/KSPL) // 128 n per CTA

typedef unsigned long long u64;

// split-K partial results: [b][ks][m=192][j=64]
__device__ float g_partial[BB * KSPL * MROWS * NG];

__device__ __forceinline__ void unpack2(u64 v, float& lo, float& hi) {
    unsigned a, b;
    asm("mov.b64 {%0, %1}, %2;" : "=r"(a), "=r"(b) : "l"(v));
    lo = __uint_as_float(a);
    hi = __uint_as_float(b);
}
__device__ __forceinline__ u64 mul2(u64 a, u64 b) {
    u64 d;
    asm("mul.rn.f32x2 %0, %1, %2;" : "=l"(d) : "l"(a), "l"(b));
    return d;
}
__device__ __forceinline__ u64 fma2(u64 a, u64 b, u64 c) {
    u64 d;
    asm("fma.rn.f32x2 %0, %1, %2, %3;" : "=l"(d) : "l"(a), "l"(b), "l"(c));
    return d;
}

// ---------------------------------------------------------------------------
// Kernel A: fused exp + per-batch split-K GEMM with packed f32x2 FMA.
//   Pd[n,2j] = Pd[n,2j+1] = exp(-0.5*(xs[j]-Xx)^2/l^2)   (pre-duplicated)
//   Q [n,i]  = exp(-0.5*(ys[i]-Xy)^2/l^2)
//   eyd[n]   = {y0,y0,y1,y1}
//   C[i*3+c, j] += sum_n Q[n,i]*ey_c[n]*P[n,j]
// Thread tile: 6 m-rows (i pair 2r,2r+1 x 3 ch) x 8 j-cols; acc paired along M.
// No manual double-buffering: ptxas pipelines the unrolled loop (regs < spill).
// ---------------------------------------------------------------------------
__global__ void __launch_bounds__(256, 1)
equiv_gemm_kernel(const float* __restrict__ X,
                  const float* __restrict__ Y,
                  const float* __restrict__ lls)
{
    extern __shared__ float sm[];
    float* Pd_sm = sm;                              // [KCH][128] dup pairs
    float* Q_sm  = sm + KCH * 128;                  // [KCH][64]
    float* eyd   = sm + KCH * 128 + KCH * 64;       // [KCH][4] {y0,y0,y1,y1}

    const int ks  = blockIdx.x;
    const int b   = blockIdx.y;
    const int tid = threadIdx.x;
    const int n0  = ks * KCH;

    const float invl2 = __expf(-2.0f * lls[0]);   // 1 / l^2
    const float step  = 20.0f / 63.0f;

    // ---- Phase A: Pd (duplicated), Q, eyd. Two threads per n-row. ----
    {
        const int nl = tid >> 1;
        const int wh = tid & 1;
        const int j0 = wh * 32;
        const int n  = b * NCTX + n0 + nl;
        const float xx = X[2 * n];
        const float xy = X[2 * n + 1];
        float* pr = Pd_sm + nl * 128;
        float* qr = Q_sm + nl * 64;
        #pragma unroll 8
        for (int j = j0; j < j0 + 32; ++j) {
            const float gx = -10.0f + (float)j * step;   // xs[j]
            const float gy =  10.0f - (float)j * step;   // ys[i]
            const float dx = gx - xx;
            const float dy = gy - xy;
            const float p  = __expf(-0.5f * dx * dx * invl2);
            pr[2 * j]     = p;
            pr[2 * j + 1] = p;
            qr[j] = __expf(-0.5f * dy * dy * invl2);
        }
        const float yv = Y[2 * n + wh];
        eyd[nl * 4 + 2 * wh]     = yv;
        eyd[nl * 4 + 2 * wh + 1] = yv;
    }
    __syncthreads();

    // ---- Phase B: GEMM with f32x2 packed FMA ----
    const int r  = tid & 31;    // m-tile: rows 6r..6r+5 (i = 2r, 2r+1)
    const int jb = (tid >> 5) * 8;

    u64 acc[3][8];
    #pragma unroll
    for (int c = 0; c < 3; ++c)
        #pragma unroll
        for (int v = 0; v < 8; ++v)
            acc[c][v] = 0ULL;

    const float* qp = Q_sm + 2 * r;
    const float* pp = Pd_sm + 2 * jb;

    #pragma unroll 4
    for (int k = 0; k < KCH; ++k) {
        const u64        qq = *(const u64*)(qp + k * 64);
        const ulonglong2 ey = *(const ulonglong2*)(eyd + k * 4);
        const ulonglong2 pA = *(const ulonglong2*)(pp + k * 128);
        const ulonglong2 pB = *(const ulonglong2*)(pp + k * 128 + 4);
        const ulonglong2 pC = *(const ulonglong2*)(pp + k * 128 + 8);
        const ulonglong2 pD = *(const ulonglong2*)(pp + k * 128 + 12);

        const u64 m1 = mul2(qq, ey.x);   // {q0*y0, q1*y0}
        const u64 m2 = mul2(qq, ey.y);   // {q0*y1, q1*y1}

        const u64 pd[8] = {pA.x, pA.y, pB.x, pB.y, pC.x, pC.y, pD.x, pD.y};
        #pragma unroll
        for (int v = 0; v < 8; ++v) {
            acc[0][v] = fma2(qq, pd[v], acc[0][v]);
            acc[1][v] = fma2(m1, pd[v], acc[1][v]);
            acc[2][v] = fma2(m2, pd[v], acc[2][v]);
        }
    }
    __syncthreads();

    // ---- Epilogue: stage C in smem (reuse Pd region), coalesced store ----
    float* C_sm = sm;   // 192*64 = 12288 floats
    #pragma unroll
    for (int c = 0; c < 3; ++c)
        #pragma unroll
        for (int v = 0; v < 8; ++v) {
            float lo, hi;
            unpack2(acc[c][v], lo, hi);
            C_sm[(6 * r + c)     * 64 + jb + v] = lo;   // i = 2r
            C_sm[(6 * r + 3 + c) * 64 + jb + v] = hi;   // i = 2r+1
        }
    __syncthreads();

    float4* dst = (float4*)(g_partial + (size_t)(b * KSPL + ks) * (MROWS * NG));
    const float4* src = (const float4*)C_sm;
    #pragma unroll
    for (int idx = tid; idx < MROWS * NG / 4; idx += 256)
        dst[idx] = src[idx];
}

// ---------------------------------------------------------------------------
// Kernel B: reduce split-K partials. One thread per (channel, b, i, j4):
// 49152 threads for 3x the parallelism of the per-(b,i,j4) version.
// Channels 1/2 re-read the channel-0 partials to compute the density divide
// (extra reads are L2-resident in the timed run).
// ---------------------------------------------------------------------------
__global__ void __launch_bounds__(128)
equiv_reduce_kernel(float* __restrict__ out)
{
    const int t   = blockIdx.x * 128 + threadIdx.x;   // 49152
    const int ch  = t >> 14;                          // 0..2
    const int rem = t & 16383;                        // b*1024 + i*16 + j4idx
    const int b   = rem >> 10;
    const int pos = rem & 1023;
    const int i   = pos >> 4;
    const int j4  = (pos & 15) * 4;

    const float* base = g_partial + ((size_t)b * KSPL * MROWS + i * 3) * NG + j4;

    float4 s = make_float4(0.f, 0.f, 0.f, 0.f);
    #pragma unroll
    for (int sk = 0; sk < KSPL; ++sk) {
        const float4 v = *(const float4*)(base + (size_t)sk * MROWS * NG + ch * NG);
        s.x += v.x; s.y += v.y; s.z += v.z; s.w += v.w;
    }

    float4 o = s;
    if (ch != 0) {
        float4 d = make_float4(0.f, 0.f, 0.f, 0.f);
        #pragma unroll
        for (int sk = 0; sk < KSPL; ++sk) {
            const float4 v = *(const float4*)(base + (size_t)sk * MROWS * NG);
            d.x += v.x; d.y += v.y; d.z += v.z; d.w += v.w;
        }
        o = make_float4(s.x / d.x, s.y / d.y, s.z / d.z, s.w / d.w);
    }

    *(float4*)&out[(b * 3 + ch) * 4096 + i * 64 + j4] = o;
}

// ---------------------------------------------------------------------------
extern "C" void kernel_launch(void* const* d_in, const int* in_sizes, int n_in,
                              void* d_out, int out_size)
{
    const float* X   = (const float*)d_in[0];
    const float* Y   = (const float*)d_in[1];
    const float* lls = (const float*)d_in[2];
    float* out = (float*)d_out;

    const size_t smem_bytes = (size_t)(KCH * 128 + KCH * 64 + KCH * 4) * sizeof(float); // 100352
    cudaFuncSetAttribute(equiv_gemm_kernel,
                         cudaFuncAttributeMaxDynamicSharedMemorySize,
                         (int)smem_bytes);

    equiv_gemm_kernel<<<dim3(KSPL, BB), 256, smem_bytes>>>(X, Y, lls);
    equiv_reduce_kernel<<<(3 * BB * NG * NG / 4) / 128, 128>>>(out);
}